// round 13
// baseline (speedup 1.0000x reference)
#include <cuda_runtime.h>
#include <cuda_fp16.h>
#include <cuda_pipeline_primitives.h>
#include <mma.h>
#include <stdint.h>

using namespace nvcuda;

// Problem constants (fixed by the dataset)
#define FIN   256
#define FQK   256
#define NQK   (2 * FQK)          // 512
#define MAXN  20000
#define MROWS 20096              // 157 * 128, padded for unguarded tiles
#define SCALING 0.0625f          // FQK^-0.5

// Scratch (no allocation allowed in kernel_launch)
__device__ __half g_qh[(size_t)MROWS * FQK];     // q half, fp16 (scaled)
__device__ __half g_kh[(size_t)MROWS * FQK];     // k half, fp16
__device__ __half g_xh[(size_t)MROWS * FIN];     // x in fp16
__device__ __half g_wh[(size_t)NQK * FIN];       // W in fp16
__device__ int    g_rowptr[MAXN + 1];            // CSR row offsets

// ===========================================================================
// Kernel 0: fp32 -> fp16 convert. One thread per float4.
// ===========================================================================
__global__ __launch_bounds__(256)
void convert_kernel(const float* __restrict__ src,
                    __half* __restrict__ dst,
                    int n4)
{
    const int i = blockIdx.x * blockDim.x + threadIdx.x;
    if (i >= n4) return;
    float4 v = ((const float4*)src)[i];
    ((__half2*)dst)[2 * i]     = __halves2half2(__float2half(v.x), __float2half(v.y));
    ((__half2*)dst)[2 * i + 1] = __halves2half2(__float2half(v.z), __float2half(v.w));
}

// ===========================================================================
// Kernel 0c: rowptr[v] = lower_bound(src, v) via boundary scan over sorted src.
// ===========================================================================
__global__ __launch_bounds__(256)
void rowptr_kernel(const int* __restrict__ src,
                   int* __restrict__ rowptr,
                   int E, int N)
{
    const int e = blockIdx.x * blockDim.x + threadIdx.x;
    if (e >= E) return;
    const int s = src[e];
    if (e == 0) {
        for (int v = 0; v <= s; ++v) rowptr[v] = 0;
    } else {
        const int sp = src[e - 1];
        for (int v = sp + 1; v <= s; ++v) rowptr[v] = e;
    }
    if (e == E - 1) {
        for (int v = s + 1; v <= N; ++v) rowptr[v] = E;
    }
}

// ===========================================================================
// Kernel 1: qk = x @ W^T via WMMA fp16. CTA tile 128(m) x 128(n), KC=64,
// 8 warps as 4x2 (warp = 32x64 strip), cp.async double-buffered.
// __launch_bounds__(256, 3): cap regs at 84 so 3 CTAs/SM co-reside
// (24 warps/SM) — smem 3 x 73728 = 221184 B fits the 228 KB carveout.
// ===========================================================================
#define BM 128
#define BN 128
#define KC 64
#define LDS_ 72                  // padded smem leading dim (halves)

#define SA_   0
#define SB_   (SA_ + BM * LDS_)              // 9216
#define STAGE_ELEMS (SB_ + BN * LDS_)        // 18432 halves = 36864 B
#define SM_BYTES (STAGE_ELEMS * 2 * 2)       // 73728 B

__device__ __forceinline__ void load_stage(__half* sm,
                                           const __half* __restrict__ xh,
                                           const __half* __restrict__ wh,
                                           int m0, int n0, int kc, int tid)
{
#pragma unroll
    for (int i = 0; i < 4; ++i) {
        const int idx = tid + i * 256;           // 0..1023
        const int r = idx >> 3;                  // 0..127
        const int c = (idx & 7) * 8;             // 0..56
        const size_t g = (size_t)(m0 + r) * FIN + kc + c;
        __pipeline_memcpy_async(sm + SA_ + r * LDS_ + c, xh + g, 16);
    }
#pragma unroll
    for (int i = 0; i < 4; ++i) {
        const int idx = tid + i * 256;
        const int r = idx >> 3;
        const int c = (idx & 7) * 8;
        const size_t g = (size_t)(n0 + r) * FIN + kc + c;
        __pipeline_memcpy_async(sm + SB_ + r * LDS_ + c, wh + g, 16);
    }
}

__global__ __launch_bounds__(256, 3)
void gemm_qk_wmma(const __half* __restrict__ xh,
                  const __half* __restrict__ wh,
                  __half* __restrict__ qout,
                  __half* __restrict__ kout)
{
    extern __shared__ __half sm[];
    const int tid = threadIdx.x;
    const int wid = tid >> 5;
    const int lane = tid & 31;
    const int warp_m = wid >> 1;          // 0..3
    const int warp_n = wid & 1;           // 0..1
    const int m0  = blockIdx.y * BM;
    const int n0  = blockIdx.x * BN;
    const bool is_q = (n0 < FQK);
    const float scale = is_q ? SCALING : 1.0f;

    wmma::fragment<wmma::accumulator, 16, 16, 16, float> acc[2][4];
#pragma unroll
    for (int mi = 0; mi < 2; ++mi)
#pragma unroll
        for (int f = 0; f < 4; ++f) wmma::fill_fragment(acc[mi][f], 0.0f);

    load_stage(sm, xh, wh, m0, n0, 0, tid);
    __pipeline_commit();
    load_stage(sm + STAGE_ELEMS, xh, wh, m0, n0, KC, tid);
    __pipeline_commit();

    const int nChunks = FIN / KC;   // 4
    for (int c = 0; c < nChunks; ++c) {
        __pipeline_wait_prior(1);
        __syncthreads();
        __half* st = sm + (c & 1) * STAGE_ELEMS;

#pragma unroll
        for (int ks = 0; ks < KC / 16; ++ks) {
            wmma::fragment<wmma::matrix_a, 16, 16, 16, __half, wmma::row_major> ah[2];
#pragma unroll
            for (int mi = 0; mi < 2; ++mi) {
                const int row = warp_m * 32 + mi * 16;
                wmma::load_matrix_sync(ah[mi], st + SA_ + row * LDS_ + ks * 16, LDS_);
            }
#pragma unroll
            for (int nf = 0; nf < 4; ++nf) {
                const int col = warp_n * 64 + nf * 16;
                wmma::fragment<wmma::matrix_b, 16, 16, 16, __half, wmma::col_major> bh;
                wmma::load_matrix_sync(bh, st + SB_ + col * LDS_ + ks * 16, LDS_);
#pragma unroll
                for (int mi = 0; mi < 2; ++mi)
                    wmma::mma_sync(acc[mi][nf], ah[mi], bh, acc[mi][nf]);
            }
        }
        __syncthreads();
        if (c + 2 < nChunks) {
            load_stage(st, xh, wh, m0, n0, (c + 2) * KC, tid);
        }
        __pipeline_commit();
    }

    // ---- epilogue: fp32 acc -> fp16 via per-warp smem scratch ----
    __syncthreads();
    float* buf = (float*)sm + wid * (16 * 64);   // 4 KB per warp
    __half* outp = is_q ? qout : kout;
    const int col0 = (is_q ? n0 : n0 - FQK) + warp_n * 64;

#pragma unroll
    for (int mi = 0; mi < 2; ++mi) {
        const int row0 = m0 + warp_m * 32 + mi * 16;
#pragma unroll
        for (int nf = 0; nf < 4; ++nf) {
#pragma unroll
            for (int t = 0; t < acc[mi][nf].num_elements; ++t)
                acc[mi][nf].x[t] *= scale;
            wmma::store_matrix_sync(buf + nf * 16, acc[mi][nf], 64, wmma::mem_row_major);
        }
        __syncwarp();
#pragma unroll
        for (int r = 0; r < 16; ++r) {
            float a = buf[r * 64 + 2 * lane];
            float b = buf[r * 64 + 2 * lane + 1];
            ((__half2*)(outp + (size_t)(row0 + r) * FQK + col0))[lane] =
                __halves2half2(__float2half(a), __float2half(b));
        }
        __syncwarp();
    }
}

// ===========================================================================
// Kernel 2: fused edge pass (round-10 winner + precomputed rowptr).
// One warp per src node; 8 lanes per edge, 4 edges per iteration;
// 2-stage x 4-row cp.async ring in static smem. (Near L2-gather floor.)
// ===========================================================================
#define SMEM_DEG 128

// dot of 4 uint4 (32 halves) q x k per lane; 4 indep half2 accumulators
__device__ __forceinline__ float dot_h8(const uint4* q, const uint4* k)
{
    const __half2* qh = (const __half2*)q;
    const __half2* kh2 = (const __half2*)k;
    __half2 a0 = __hmul2(qh[0], kh2[0]);
    __half2 a1 = __hmul2(qh[1], kh2[1]);
    __half2 a2 = __hmul2(qh[2], kh2[2]);
    __half2 a3 = __hmul2(qh[3], kh2[3]);
#pragma unroll
    for (int i = 1; i < 4; ++i) {
        a0 = __hfma2(qh[4 * i + 0], kh2[4 * i + 0], a0);
        a1 = __hfma2(qh[4 * i + 1], kh2[4 * i + 1], a1);
        a2 = __hfma2(qh[4 * i + 2], kh2[4 * i + 2], a2);
        a3 = __hfma2(qh[4 * i + 3], kh2[4 * i + 3], a3);
    }
    float2 f0 = __half22float2(a0);
    float2 f1 = __half22float2(a1);
    float2 f2 = __half22float2(a2);
    float2 f3 = __half22float2(a3);
    return ((f0.x + f0.y) + (f1.x + f1.y)) + ((f2.x + f2.y) + (f3.x + f3.y));
}

// fill one 4-row stage: lane copies 16B per row (32 lanes cover 512B row)
__device__ __forceinline__ void fill_stage(__half (*dst)[256],
                                           const __half* __restrict__ kh,
                                           const int* __restrict__ dest,
                                           int j0, int hi, int lane)
{
#pragma unroll
    for (int r = 0; r < 4; ++r) {
        int j = j0 + r;
        if (j >= hi) j = hi - 1;
        const __half* src = kh + (size_t)dest[j] * FQK;
        __pipeline_memcpy_async(&dst[r][lane * 8], src + lane * 8, 16);
    }
}

__global__ __launch_bounds__(256)
void edge_fused_kernel(const int* __restrict__ ei,
                       const int* __restrict__ rowptr,
                       const __half* __restrict__ qh,
                       const __half* __restrict__ kh,
                       float* __restrict__ out,
                       int E, int N)
{
    // per-warp: 2 stages x 4 rows x 256 halves = 4 KB ring + 512 B exbuf
    __shared__ __half kbuf[8][2][4][256];       // 32 KB
    __shared__ float exbuf[8][SMEM_DEG];        // 4 KB

    const int wslot = threadIdx.x >> 5;
    const int node  = (blockIdx.x * blockDim.x + threadIdx.x) >> 5;
    const int lane  = threadIdx.x & 31;
    const int g     = lane >> 3;          // edge slot 0..3
    const int u     = lane & 7;           // chunk owner within 8-lane group
    if (node >= N) return;

    const int lo = rowptr[node];
    const int hi = rowptr[node + 1];
    const int deg = hi - lo;
    if (deg <= 0) return;

    // lane u owns uint4s {u, u+8, u+16, u+24} of the 32-uint4 q row
    const uint4* qp = (const uint4*)(qh + (size_t)node * FQK);
    uint4 qr[4];
#pragma unroll
    for (int i = 0; i < 4; ++i) qr[i] = qp[u + 8 * i];

    const int* __restrict__ dest = ei + E;
    const int nIter = (deg + 3) >> 2;
    const bool in_smem = (deg <= SMEM_DEG);
    float* exdst = in_smem ? &exbuf[wslot][0] : &out[lo];
    float sum = 0.0f;

    // prologue: fill both stages
    fill_stage(kbuf[wslot][0], kh, dest, lo, hi, lane);
    __pipeline_commit();
    fill_stage(kbuf[wslot][1], kh, dest, lo + 4, hi, lane);
    __pipeline_commit();

    for (int it = 0; it < nIter; ++it) {
        __pipeline_wait_prior(1);
        __syncwarp();

        // group g consumes row g of the current stage
        const uint4* rp = (const uint4*)kbuf[wslot][it & 1][g];
        uint4 cr[4];
#pragma unroll
        for (int i = 0; i < 4; ++i) cr[i] = rp[u + 8 * i];

        __syncwarp();   // all reads done before the stage is refilled
        fill_stage(kbuf[wslot][it & 1], kh, dest, lo + 4 * (it + 2), hi, lane);
        __pipeline_commit();

        float p = dot_h8(qr, cr);
#pragma unroll
        for (int o = 1; o < 8; o <<= 1)
            p += __shfl_xor_sync(0xffffffffu, p, o);

        const int j = lo + 4 * it + g;
        if (j < hi) {
            float ex = __expf(p);
            sum += ex;
            if (u == 0) exdst[j - lo] = ex;
        }
    }

    // combine the four group sums (deterministic order)
    sum += __shfl_xor_sync(0xffffffffu, sum, 8);
    sum += __shfl_xor_sync(0xffffffffu, sum, 16);
    const float inv = 1.0f / sum;

    if (in_smem) {
        __syncwarp();
        for (int i = lane; i < deg; i += 32)
            out[lo + i] = exbuf[wslot][i] * inv;
    } else {
        __threadfence_block();
        __syncwarp();
        for (int i = lane; i < deg; i += 32)
            out[lo + i] *= inv;
    }
}

// ===========================================================================
extern "C" void kernel_launch(void* const* d_in, const int* in_sizes, int n_in,
                              void* d_out, int out_size)
{
    const float* x   = (const float*)d_in[0];
    const int*   ei  = (const int*)d_in[1];
    const float* W   = (const float*)d_in[2];
    float*       out = (float*)d_out;

    const int N = in_sizes[0] / FIN;     // 20000
    const int E = in_sizes[1] / 2;       // 640000

    __half* qht; cudaGetSymbolAddress((void**)&qht, g_qh);
    __half* kht; cudaGetSymbolAddress((void**)&kht, g_kh);
    __half* xh;  cudaGetSymbolAddress((void**)&xh,  g_xh);
    __half* wh;  cudaGetSymbolAddress((void**)&wh,  g_wh);
    int* rowptr; cudaGetSymbolAddress((void**)&rowptr, g_rowptr);

    // 0) convert x, W -> fp16; build rowptr from sorted src
    {
        int n4x = N * FIN / 4;
        convert_kernel<<<(n4x + 255) / 256, 256>>>(x, xh, n4x);
        int n4w = NQK * FIN / 4;
        convert_kernel<<<(n4w + 255) / 256, 256>>>(W, wh, n4w);
        rowptr_kernel<<<(E + 255) / 256, 256>>>(ei, rowptr, E, N);
    }
    // 1) projection GEMM (fp16 WMMA, cp.async double-buffered, 3 CTA/SM)
    {
        cudaFuncSetAttribute(gemm_qk_wmma,
                             cudaFuncAttributeMaxDynamicSharedMemorySize,
                             SM_BYTES);
        dim3 grid(NQK / BN, MROWS / BM);
        gemm_qk_wmma<<<grid, 256, SM_BYTES>>>(xh, wh, qht, kht);
    }
    // 2) fused edge dot + scatter softmax (one warp per node, 2-stage ring)
    {
        int blocks = (N * 32 + 255) / 256;
        edge_fused_kernel<<<blocks, 256>>>(ei, rowptr, qht, kht, out, E, N);
    }
}

// round 14
// speedup vs baseline: 1.1100x; 1.1100x over previous
#include <cuda_runtime.h>
#include <cuda_fp16.h>
#include <cuda_pipeline_primitives.h>
#include <mma.h>
#include <stdint.h>

using namespace nvcuda;

// Problem constants (fixed by the dataset)
#define FIN   256
#define FQK   256
#define NQK   (2 * FQK)          // 512
#define MAXN  20000
#define MROWS 20096              // 157 * 128, padded for unguarded tiles
#define SCALING 0.0625f          // FQK^-0.5

// Scratch (no allocation allowed in kernel_launch)
__device__ __half g_qh[(size_t)MROWS * FQK];     // q half, fp16 (scaled)
__device__ __half g_kh[(size_t)MROWS * FQK];     // k half, fp16
__device__ __half g_xh[(size_t)MROWS * FIN];     // x in fp16
__device__ __half g_wh[(size_t)NQK * FIN];       // W in fp16
__device__ int    g_rowptr[MAXN + 1];            // CSR row offsets

// ===========================================================================
// Kernel 0: fp32 -> fp16 convert. One thread per float4.
// ===========================================================================
__global__ __launch_bounds__(256)
void convert_kernel(const float* __restrict__ src,
                    __half* __restrict__ dst,
                    int n4)
{
    const int i = blockIdx.x * blockDim.x + threadIdx.x;
    if (i >= n4) return;
    float4 v = ((const float4*)src)[i];
    ((__half2*)dst)[2 * i]     = __halves2half2(__float2half(v.x), __float2half(v.y));
    ((__half2*)dst)[2 * i + 1] = __halves2half2(__float2half(v.z), __float2half(v.w));
}

// ===========================================================================
// Kernel 0c: rowptr[v] = lower_bound(src, v) via boundary scan over sorted src.
// ===========================================================================
__global__ __launch_bounds__(256)
void rowptr_kernel(const int* __restrict__ src,
                   int* __restrict__ rowptr,
                   int E, int N)
{
    const int e = blockIdx.x * blockDim.x + threadIdx.x;
    if (e >= E) return;
    const int s = src[e];
    if (e == 0) {
        for (int v = 0; v <= s; ++v) rowptr[v] = 0;
    } else {
        const int sp = src[e - 1];
        for (int v = sp + 1; v <= s; ++v) rowptr[v] = e;
    }
    if (e == E - 1) {
        for (int v = s + 1; v <= N; ++v) rowptr[v] = E;
    }
}

// ===========================================================================
// Kernel 1: qk = x @ W^T via WMMA fp16. CTA tile 128(m) x 128(n), KC=64.
// 512 threads / 16 warps as 8x2; warp tile 16(m) x 64(n) -> only 4 acc
// fragments (32 regs) per warp => low reg footprint, 32 warps/SM at
// 2 CTAs/SM. cp.async double-buffered. Output fp16 (q scaled, k plain).
// ===========================================================================
#define GEMM_THREADS 512
#define BM 128
#define BN 128
#define KC 64
#define LDS_ 72                  // padded smem leading dim (halves)

#define SA_   0
#define SB_   (SA_ + BM * LDS_)              // 9216
#define STAGE_ELEMS (SB_ + BN * LDS_)        // 18432 halves = 36864 B
#define SM_BYTES (STAGE_ELEMS * 2 * 2)       // 73728 B

__device__ __forceinline__ void load_stage(__half* sm,
                                           const __half* __restrict__ xh,
                                           const __half* __restrict__ wh,
                                           int m0, int n0, int kc, int tid)
{
    // A tile: 128 rows x 64 halves = 1024 x 16B chunks; 512 threads x 2
#pragma unroll
    for (int i = 0; i < 2; ++i) {
        const int idx = tid + i * GEMM_THREADS;  // 0..1023
        const int r = idx >> 3;                  // 0..127
        const int c = (idx & 7) * 8;             // 0..56
        const size_t g = (size_t)(m0 + r) * FIN + kc + c;
        __pipeline_memcpy_async(sm + SA_ + r * LDS_ + c, xh + g, 16);
    }
    // B tile: 128 rows x 64 halves
#pragma unroll
    for (int i = 0; i < 2; ++i) {
        const int idx = tid + i * GEMM_THREADS;
        const int r = idx >> 3;
        const int c = (idx & 7) * 8;
        const size_t g = (size_t)(n0 + r) * FIN + kc + c;
        __pipeline_memcpy_async(sm + SB_ + r * LDS_ + c, wh + g, 16);
    }
}

__global__ __launch_bounds__(GEMM_THREADS)
void gemm_qk_wmma(const __half* __restrict__ xh,
                  const __half* __restrict__ wh,
                  __half* __restrict__ qout,
                  __half* __restrict__ kout)
{
    extern __shared__ __half sm[];
    const int tid = threadIdx.x;
    const int wid = tid >> 5;             // 0..15
    const int lane = tid & 31;
    const int warp_m = wid >> 1;          // 0..7  (16 rows each)
    const int warp_n = wid & 1;           // 0..1  (64 cols each)
    const int m0  = blockIdx.y * BM;
    const int n0  = blockIdx.x * BN;
    const bool is_q = (n0 < FQK);
    const float scale = is_q ? SCALING : 1.0f;

    wmma::fragment<wmma::accumulator, 16, 16, 16, float> acc[4];
#pragma unroll
    for (int f = 0; f < 4; ++f) wmma::fill_fragment(acc[f], 0.0f);

    load_stage(sm, xh, wh, m0, n0, 0, tid);
    __pipeline_commit();
    load_stage(sm + STAGE_ELEMS, xh, wh, m0, n0, KC, tid);
    __pipeline_commit();

    const int nChunks = FIN / KC;   // 4
    for (int c = 0; c < nChunks; ++c) {
        __pipeline_wait_prior(1);
        __syncthreads();
        __half* st = sm + (c & 1) * STAGE_ELEMS;

        const __half* aRow = st + SA_ + warp_m * 16 * LDS_;
#pragma unroll
        for (int ks = 0; ks < KC / 16; ++ks) {
            wmma::fragment<wmma::matrix_a, 16, 16, 16, __half, wmma::row_major> ah;
            wmma::load_matrix_sync(ah, aRow + ks * 16, LDS_);
#pragma unroll
            for (int nf = 0; nf < 4; ++nf) {
                const int col = warp_n * 64 + nf * 16;
                wmma::fragment<wmma::matrix_b, 16, 16, 16, __half, wmma::col_major> bh;
                wmma::load_matrix_sync(bh, st + SB_ + col * LDS_ + ks * 16, LDS_);
                wmma::mma_sync(acc[nf], ah, bh, acc[nf]);
            }
        }
        __syncthreads();
        if (c + 2 < nChunks) {
            load_stage(st, xh, wh, m0, n0, (c + 2) * KC, tid);
        }
        __pipeline_commit();
    }

    // ---- epilogue: fp32 acc -> fp16 via per-warp smem scratch ----
    __syncthreads();   // mainloop smem reads done; reuse as scratch
    float* buf = (float*)sm + wid * (16 * 64);   // 4 KB per warp, 64 KB total
    __half* outp = is_q ? qout : kout;
    const int col0 = (is_q ? n0 : n0 - FQK) + warp_n * 64;
    const int row0 = m0 + warp_m * 16;

#pragma unroll
    for (int nf = 0; nf < 4; ++nf) {
#pragma unroll
        for (int t = 0; t < acc[nf].num_elements; ++t)
            acc[nf].x[t] *= scale;
        wmma::store_matrix_sync(buf + nf * 16, acc[nf], 64, wmma::mem_row_major);
    }
    __syncwarp();
#pragma unroll
    for (int r = 0; r < 16; ++r) {
        float a = buf[r * 64 + 2 * lane];
        float b = buf[r * 64 + 2 * lane + 1];
        ((__half2*)(outp + (size_t)(row0 + r) * FQK + col0))[lane] =
            __halves2half2(__float2half(a), __float2half(b));
    }
}

// ===========================================================================
// Kernel 2: fused edge pass (round-12 winner, unchanged).
// One warp per src node; 8 lanes per edge, 4 edges per iteration;
// 2-stage x 4-row cp.async ring in static smem; precomputed rowptr.
// ===========================================================================
#define SMEM_DEG 128

__device__ __forceinline__ float dot_h8(const uint4* q, const uint4* k)
{
    const __half2* qh = (const __half2*)q;
    const __half2* kh2 = (const __half2*)k;
    __half2 a0 = __hmul2(qh[0], kh2[0]);
    __half2 a1 = __hmul2(qh[1], kh2[1]);
    __half2 a2 = __hmul2(qh[2], kh2[2]);
    __half2 a3 = __hmul2(qh[3], kh2[3]);
#pragma unroll
    for (int i = 1; i < 4; ++i) {
        a0 = __hfma2(qh[4 * i + 0], kh2[4 * i + 0], a0);
        a1 = __hfma2(qh[4 * i + 1], kh2[4 * i + 1], a1);
        a2 = __hfma2(qh[4 * i + 2], kh2[4 * i + 2], a2);
        a3 = __hfma2(qh[4 * i + 3], kh2[4 * i + 3], a3);
    }
    float2 f0 = __half22float2(a0);
    float2 f1 = __half22float2(a1);
    float2 f2 = __half22float2(a2);
    float2 f3 = __half22float2(a3);
    return ((f0.x + f0.y) + (f1.x + f1.y)) + ((f2.x + f2.y) + (f3.x + f3.y));
}

__device__ __forceinline__ void fill_stage(__half (*dst)[256],
                                           const __half* __restrict__ kh,
                                           const int* __restrict__ dest,
                                           int j0, int hi, int lane)
{
#pragma unroll
    for (int r = 0; r < 4; ++r) {
        int j = j0 + r;
        if (j >= hi) j = hi - 1;
        const __half* src = kh + (size_t)dest[j] * FQK;
        __pipeline_memcpy_async(&dst[r][lane * 8], src + lane * 8, 16);
    }
}

__global__ __launch_bounds__(256)
void edge_fused_kernel(const int* __restrict__ ei,
                       const int* __restrict__ rowptr,
                       const __half* __restrict__ qh,
                       const __half* __restrict__ kh,
                       float* __restrict__ out,
                       int E, int N)
{
    __shared__ __half kbuf[8][2][4][256];       // 32 KB
    __shared__ float exbuf[8][SMEM_DEG];        // 4 KB

    const int wslot = threadIdx.x >> 5;
    const int node  = (blockIdx.x * blockDim.x + threadIdx.x) >> 5;
    const int lane  = threadIdx.x & 31;
    const int g     = lane >> 3;          // edge slot 0..3
    const int u     = lane & 7;           // chunk owner within 8-lane group
    if (node >= N) return;

    const int lo = rowptr[node];
    const int hi = rowptr[node + 1];
    const int deg = hi - lo;
    if (deg <= 0) return;

    const uint4* qp = (const uint4*)(qh + (size_t)node * FQK);
    uint4 qr[4];
#pragma unroll
    for (int i = 0; i < 4; ++i) qr[i] = qp[u + 8 * i];

    const int* __restrict__ dest = ei + E;
    const int nIter = (deg + 3) >> 2;
    const bool in_smem = (deg <= SMEM_DEG);
    float* exdst = in_smem ? &exbuf[wslot][0] : &out[lo];
    float sum = 0.0f;

    fill_stage(kbuf[wslot][0], kh, dest, lo, hi, lane);
    __pipeline_commit();
    fill_stage(kbuf[wslot][1], kh, dest, lo + 4, hi, lane);
    __pipeline_commit();

    for (int it = 0; it < nIter; ++it) {
        __pipeline_wait_prior(1);
        __syncwarp();

        const uint4* rp = (const uint4*)kbuf[wslot][it & 1][g];
        uint4 cr[4];
#pragma unroll
        for (int i = 0; i < 4; ++i) cr[i] = rp[u + 8 * i];

        __syncwarp();
        fill_stage(kbuf[wslot][it & 1], kh, dest, lo + 4 * (it + 2), hi, lane);
        __pipeline_commit();

        float p = dot_h8(qr, cr);
#pragma unroll
        for (int o = 1; o < 8; o <<= 1)
            p += __shfl_xor_sync(0xffffffffu, p, o);

        const int j = lo + 4 * it + g;
        if (j < hi) {
            float ex = __expf(p);
            sum += ex;
            if (u == 0) exdst[j - lo] = ex;
        }
    }

    sum += __shfl_xor_sync(0xffffffffu, sum, 8);
    sum += __shfl_xor_sync(0xffffffffu, sum, 16);
    const float inv = 1.0f / sum;

    if (in_smem) {
        __syncwarp();
        for (int i = lane; i < deg; i += 32)
            out[lo + i] = exbuf[wslot][i] * inv;
    } else {
        __threadfence_block();
        __syncwarp();
        for (int i = lane; i < deg; i += 32)
            out[lo + i] *= inv;
    }
}

// ===========================================================================
extern "C" void kernel_launch(void* const* d_in, const int* in_sizes, int n_in,
                              void* d_out, int out_size)
{
    const float* x   = (const float*)d_in[0];
    const int*   ei  = (const int*)d_in[1];
    const float* W   = (const float*)d_in[2];
    float*       out = (float*)d_out;

    const int N = in_sizes[0] / FIN;     // 20000
    const int E = in_sizes[1] / 2;       // 640000

    __half* qht; cudaGetSymbolAddress((void**)&qht, g_qh);
    __half* kht; cudaGetSymbolAddress((void**)&kht, g_kh);
    __half* xh;  cudaGetSymbolAddress((void**)&xh,  g_xh);
    __half* wh;  cudaGetSymbolAddress((void**)&wh,  g_wh);
    int* rowptr; cudaGetSymbolAddress((void**)&rowptr, g_rowptr);

    // 0) convert x, W -> fp16; build rowptr from sorted src
    {
        int n4x = N * FIN / 4;
        convert_kernel<<<(n4x + 255) / 256, 256>>>(x, xh, n4x);
        int n4w = NQK * FIN / 4;
        convert_kernel<<<(n4w + 255) / 256, 256>>>(W, wh, n4w);
        rowptr_kernel<<<(E + 255) / 256, 256>>>(ei, rowptr, E, N);
    }
    // 1) projection GEMM (fp16 WMMA, 512 threads, cp.async x2)
    {
        cudaFuncSetAttribute(gemm_qk_wmma,
                             cudaFuncAttributeMaxDynamicSharedMemorySize,
                             SM_BYTES);
        dim3 grid(NQK / BN, MROWS / BM);
        gemm_qk_wmma<<<grid, GEMM_THREADS, SM_BYTES>>>(xh, wh, qht, kht);
    }
    // 2) fused edge dot + scatter softmax (one warp per node, 2-stage ring)
    {
        int blocks = (N * 32 + 255) / 256;
        edge_fused_kernel<<<blocks, 256>>>(ei, rowptr, qht, kht, out, E, N);
    }
}

// round 15
// speedup vs baseline: 1.2167x; 1.0961x over previous
#include <cuda_runtime.h>
#include <cuda_fp16.h>
#include <cuda_pipeline_primitives.h>
#include <mma.h>
#include <stdint.h>

using namespace nvcuda;

// Problem constants (fixed by the dataset)
#define FIN   256
#define FQK   256
#define NQK   (2 * FQK)          // 512
#define MAXN  20000
#define MROWS 20096              // 157 * 128, padded for unguarded tiles
#define SCALING 0.0625f          // FQK^-0.5

// Scratch (no allocation allowed in kernel_launch)
__device__ __half g_qh[(size_t)MROWS * FQK];     // q half, fp16 (scaled)
__device__ __half g_kh[(size_t)MROWS * FQK];     // k half, fp16
__device__ __half g_xh[(size_t)MROWS * FIN];     // x in fp16
__device__ __half g_wh[(size_t)NQK * FIN];       // W in fp16
__device__ int    g_rowptr[MAXN + 1];            // CSR row offsets

// ===========================================================================
// Kernel 0 (fused prologue): convert x -> fp16, convert W -> fp16, and build
// rowptr from the sorted src array — one launch, partitioned by blockIdx.
//   blocks [0, XB)          : x convert  (n4x float4s)
//   blocks [XB, XB+WB)      : W convert  (n4w float4s)
//   blocks [XB+WB, ...)     : rowptr boundary scan (E edges)
// ===========================================================================
__device__ __forceinline__ void convert4(const float* __restrict__ src,
                                         __half* __restrict__ dst, int i)
{
    float4 v = ((const float4*)src)[i];
    ((__half2*)dst)[2 * i]     = __halves2half2(__float2half(v.x), __float2half(v.y));
    ((__half2*)dst)[2 * i + 1] = __halves2half2(__float2half(v.z), __float2half(v.w));
}

__global__ __launch_bounds__(256)
void prologue_kernel(const float* __restrict__ x,
                     const float* __restrict__ W,
                     const int* __restrict__ src,
                     __half* __restrict__ xh,
                     __half* __restrict__ wh,
                     int* __restrict__ rowptr,
                     int n4x, int n4w, int E, int N, int XB, int WB)
{
    const int b = blockIdx.x;
    if (b < XB) {
        const int i = b * 256 + threadIdx.x;
        if (i < n4x) convert4(x, xh, i);
    } else if (b < XB + WB) {
        const int i = (b - XB) * 256 + threadIdx.x;
        if (i < n4w) convert4(W, wh, i);
    } else {
        const int e = (b - XB - WB) * 256 + threadIdx.x;
        if (e >= E) return;
        const int s = src[e];
        if (e == 0) {
            for (int v = 0; v <= s; ++v) rowptr[v] = 0;
        } else {
            const int sp = src[e - 1];
            for (int v = sp + 1; v <= s; ++v) rowptr[v] = e;
        }
        if (e == E - 1) {
            for (int v = s + 1; v <= N; ++v) rowptr[v] = E;
        }
    }
}

// ===========================================================================
// Kernel 1: qk = x @ W^T via WMMA fp16 — ROUND-12 CONFIG (best measured).
// CTA tile 128(m) x 128(n), KC=64, 8 warps as 4x2 (warp = 32x64 strip),
// cp.async double-buffered. Output fp16 (q scaled, k plain).
// ===========================================================================
#define BM 128
#define BN 128
#define KC 64
#define LDS_ 72                  // padded smem leading dim (halves)

#define SA_   0
#define SB_   (SA_ + BM * LDS_)              // 9216
#define STAGE_ELEMS (SB_ + BN * LDS_)        // 18432 halves = 36864 B
#define SM_BYTES (STAGE_ELEMS * 2 * 2)       // 73728 B

__device__ __forceinline__ void load_stage(__half* sm,
                                           const __half* __restrict__ xh,
                                           const __half* __restrict__ wh,
                                           int m0, int n0, int kc, int tid)
{
#pragma unroll
    for (int i = 0; i < 4; ++i) {
        const int idx = tid + i * 256;           // 0..1023
        const int r = idx >> 3;                  // 0..127
        const int c = (idx & 7) * 8;             // 0..56
        const size_t g = (size_t)(m0 + r) * FIN + kc + c;
        __pipeline_memcpy_async(sm + SA_ + r * LDS_ + c, xh + g, 16);
    }
#pragma unroll
    for (int i = 0; i < 4; ++i) {
        const int idx = tid + i * 256;
        const int r = idx >> 3;
        const int c = (idx & 7) * 8;
        const size_t g = (size_t)(n0 + r) * FIN + kc + c;
        __pipeline_memcpy_async(sm + SB_ + r * LDS_ + c, wh + g, 16);
    }
}

__global__ __launch_bounds__(256)
void gemm_qk_wmma(const __half* __restrict__ xh,
                  const __half* __restrict__ wh,
                  __half* __restrict__ qout,
                  __half* __restrict__ kout)
{
    extern __shared__ __half sm[];
    const int tid = threadIdx.x;
    const int wid = tid >> 5;
    const int lane = tid & 31;
    const int warp_m = wid >> 1;          // 0..3
    const int warp_n = wid & 1;           // 0..1
    const int m0  = blockIdx.y * BM;
    const int n0  = blockIdx.x * BN;
    const bool is_q = (n0 < FQK);
    const float scale = is_q ? SCALING : 1.0f;

    wmma::fragment<wmma::accumulator, 16, 16, 16, float> acc[2][4];
#pragma unroll
    for (int mi = 0; mi < 2; ++mi)
#pragma unroll
        for (int f = 0; f < 4; ++f) wmma::fill_fragment(acc[mi][f], 0.0f);

    load_stage(sm, xh, wh, m0, n0, 0, tid);
    __pipeline_commit();
    load_stage(sm + STAGE_ELEMS, xh, wh, m0, n0, KC, tid);
    __pipeline_commit();

    const int nChunks = FIN / KC;   // 4
    for (int c = 0; c < nChunks; ++c) {
        __pipeline_wait_prior(1);
        __syncthreads();
        __half* st = sm + (c & 1) * STAGE_ELEMS;

#pragma unroll
        for (int ks = 0; ks < KC / 16; ++ks) {
            wmma::fragment<wmma::matrix_a, 16, 16, 16, __half, wmma::row_major> ah[2];
#pragma unroll
            for (int mi = 0; mi < 2; ++mi) {
                const int row = warp_m * 32 + mi * 16;
                wmma::load_matrix_sync(ah[mi], st + SA_ + row * LDS_ + ks * 16, LDS_);
            }
#pragma unroll
            for (int nf = 0; nf < 4; ++nf) {
                const int col = warp_n * 64 + nf * 16;
                wmma::fragment<wmma::matrix_b, 16, 16, 16, __half, wmma::col_major> bh;
                wmma::load_matrix_sync(bh, st + SB_ + col * LDS_ + ks * 16, LDS_);
#pragma unroll
                for (int mi = 0; mi < 2; ++mi)
                    wmma::mma_sync(acc[mi][nf], ah[mi], bh, acc[mi][nf]);
            }
        }
        __syncthreads();
        if (c + 2 < nChunks) {
            load_stage(st, xh, wh, m0, n0, (c + 2) * KC, tid);
        }
        __pipeline_commit();
    }

    // ---- epilogue: fp32 acc -> fp16 via per-warp smem scratch ----
    __syncthreads();
    float* buf = (float*)sm + wid * (16 * 64);   // 4 KB per warp
    __half* outp = is_q ? qout : kout;
    const int col0 = (is_q ? n0 : n0 - FQK) + warp_n * 64;

#pragma unroll
    for (int mi = 0; mi < 2; ++mi) {
        const int row0 = m0 + warp_m * 32 + mi * 16;
#pragma unroll
        for (int nf = 0; nf < 4; ++nf) {
#pragma unroll
            for (int t = 0; t < acc[mi][nf].num_elements; ++t)
                acc[mi][nf].x[t] *= scale;
            wmma::store_matrix_sync(buf + nf * 16, acc[mi][nf], 64, wmma::mem_row_major);
        }
        __syncwarp();
#pragma unroll
        for (int r = 0; r < 16; ++r) {
            float a = buf[r * 64 + 2 * lane];
            float b = buf[r * 64 + 2 * lane + 1];
            ((__half2*)(outp + (size_t)(row0 + r) * FQK + col0))[lane] =
                __halves2half2(__float2half(a), __float2half(b));
        }
        __syncwarp();
    }
}

// ===========================================================================
// Kernel 2: fused edge pass (round-12 winner, unchanged).
// One warp per src node; 8 lanes per edge, 4 edges per iteration;
// 2-stage x 4-row cp.async ring in static smem; precomputed rowptr.
// ===========================================================================
#define SMEM_DEG 128

__device__ __forceinline__ float dot_h8(const uint4* q, const uint4* k)
{
    const __half2* qh = (const __half2*)q;
    const __half2* kh2 = (const __half2*)k;
    __half2 a0 = __hmul2(qh[0], kh2[0]);
    __half2 a1 = __hmul2(qh[1], kh2[1]);
    __half2 a2 = __hmul2(qh[2], kh2[2]);
    __half2 a3 = __hmul2(qh[3], kh2[3]);
#pragma unroll
    for (int i = 1; i < 4; ++i) {
        a0 = __hfma2(qh[4 * i + 0], kh2[4 * i + 0], a0);
        a1 = __hfma2(qh[4 * i + 1], kh2[4 * i + 1], a1);
        a2 = __hfma2(qh[4 * i + 2], kh2[4 * i + 2], a2);
        a3 = __hfma2(qh[4 * i + 3], kh2[4 * i + 3], a3);
    }
    float2 f0 = __half22float2(a0);
    float2 f1 = __half22float2(a1);
    float2 f2 = __half22float2(a2);
    float2 f3 = __half22float2(a3);
    return ((f0.x + f0.y) + (f1.x + f1.y)) + ((f2.x + f2.y) + (f3.x + f3.y));
}

__device__ __forceinline__ void fill_stage(__half (*dst)[256],
                                           const __half* __restrict__ kh,
                                           const int* __restrict__ dest,
                                           int j0, int hi, int lane)
{
#pragma unroll
    for (int r = 0; r < 4; ++r) {
        int j = j0 + r;
        if (j >= hi) j = hi - 1;
        const __half* src = kh + (size_t)dest[j] * FQK;
        __pipeline_memcpy_async(&dst[r][lane * 8], src + lane * 8, 16);
    }
}

__global__ __launch_bounds__(256)
void edge_fused_kernel(const int* __restrict__ ei,
                       const int* __restrict__ rowptr,
                       const __half* __restrict__ qh,
                       const __half* __restrict__ kh,
                       float* __restrict__ out,
                       int E, int N)
{
    __shared__ __half kbuf[8][2][4][256];       // 32 KB
    __shared__ float exbuf[8][SMEM_DEG];        // 4 KB

    const int wslot = threadIdx.x >> 5;
    const int node  = (blockIdx.x * blockDim.x + threadIdx.x) >> 5;
    const int lane  = threadIdx.x & 31;
    const int g     = lane >> 3;          // edge slot 0..3
    const int u     = lane & 7;           // chunk owner within 8-lane group
    if (node >= N) return;

    const int lo = rowptr[node];
    const int hi = rowptr[node + 1];
    const int deg = hi - lo;
    if (deg <= 0) return;

    const uint4* qp = (const uint4*)(qh + (size_t)node * FQK);
    uint4 qr[4];
#pragma unroll
    for (int i = 0; i < 4; ++i) qr[i] = qp[u + 8 * i];

    const int* __restrict__ dest = ei + E;
    const int nIter = (deg + 3) >> 2;
    const bool in_smem = (deg <= SMEM_DEG);
    float* exdst = in_smem ? &exbuf[wslot][0] : &out[lo];
    float sum = 0.0f;

    fill_stage(kbuf[wslot][0], kh, dest, lo, hi, lane);
    __pipeline_commit();
    fill_stage(kbuf[wslot][1], kh, dest, lo + 4, hi, lane);
    __pipeline_commit();

    for (int it = 0; it < nIter; ++it) {
        __pipeline_wait_prior(1);
        __syncwarp();

        const uint4* rp = (const uint4*)kbuf[wslot][it & 1][g];
        uint4 cr[4];
#pragma unroll
        for (int i = 0; i < 4; ++i) cr[i] = rp[u + 8 * i];

        __syncwarp();
        fill_stage(kbuf[wslot][it & 1], kh, dest, lo + 4 * (it + 2), hi, lane);
        __pipeline_commit();

        float p = dot_h8(qr, cr);
#pragma unroll
        for (int o = 1; o < 8; o <<= 1)
            p += __shfl_xor_sync(0xffffffffu, p, o);

        const int j = lo + 4 * it + g;
        if (j < hi) {
            float ex = __expf(p);
            sum += ex;
            if (u == 0) exdst[j - lo] = ex;
        }
    }

    sum += __shfl_xor_sync(0xffffffffu, sum, 8);
    sum += __shfl_xor_sync(0xffffffffu, sum, 16);
    const float inv = 1.0f / sum;

    if (in_smem) {
        __syncwarp();
        for (int i = lane; i < deg; i += 32)
            out[lo + i] = exbuf[wslot][i] * inv;
    } else {
        __threadfence_block();
        __syncwarp();
        for (int i = lane; i < deg; i += 32)
            out[lo + i] *= inv;
    }
}

// ===========================================================================
extern "C" void kernel_launch(void* const* d_in, const int* in_sizes, int n_in,
                              void* d_out, int out_size)
{
    const float* x   = (const float*)d_in[0];
    const int*   ei  = (const int*)d_in[1];
    const float* W   = (const float*)d_in[2];
    float*       out = (float*)d_out;

    const int N = in_sizes[0] / FIN;     // 20000
    const int E = in_sizes[1] / 2;       // 640000

    __half* qht; cudaGetSymbolAddress((void**)&qht, g_qh);
    __half* kht; cudaGetSymbolAddress((void**)&kht, g_kh);
    __half* xh;  cudaGetSymbolAddress((void**)&xh,  g_xh);
    __half* wh;  cudaGetSymbolAddress((void**)&wh,  g_wh);
    int* rowptr; cudaGetSymbolAddress((void**)&rowptr, g_rowptr);

    // 0) fused prologue: convert x, convert W, build rowptr — one launch
    {
        const int n4x = N * FIN / 4;                  // 1,280,000
        const int n4w = NQK * FIN / 4;                // 32,768
        const int XB = (n4x + 255) / 256;             // 5000
        const int WB = (n4w + 255) / 256;             // 128
        const int RB = (E + 255) / 256;               // 2500
        prologue_kernel<<<XB + WB + RB, 256>>>(x, W, ei, xh, wh, rowptr,
                                               n4x, n4w, E, N, XB, WB);
    }
    // 1) projection GEMM (fp16 WMMA, round-12 config)
    {
        cudaFuncSetAttribute(gemm_qk_wmma,
                             cudaFuncAttributeMaxDynamicSharedMemorySize,
                             SM_BYTES);
        dim3 grid(NQK / BN, MROWS / BM);
        gemm_qk_wmma<<<grid, 256, SM_BYTES>>>(xh, wh, qht, kht);
    }
    // 2) fused edge dot + scatter softmax (one warp per node, 2-stage ring)
    {
        int blocks = (N * 32 + 255) / 256;
        edge_fused_kernel<<<blocks, 256>>>(ei, rowptr, qht, kht, out, E, N);
    }
}

// round 16
// speedup vs baseline: 1.2236x; 1.0057x over previous
#include <cuda_runtime.h>
#include <cuda_fp16.h>
#include <cuda_pipeline_primitives.h>
#include <stdint.h>

// Problem constants (fixed by the dataset)
#define FIN   256
#define FQK   256
#define NQK   (2 * FQK)          // 512
#define MAXN  20000
#define MROWS 20096              // 157 * 128, padded for unguarded tiles
#define SCALING 0.0625f          // FQK^-0.5

// Scratch (no allocation allowed in kernel_launch)
__device__ __half g_qh[(size_t)MROWS * FQK];     // q half, fp16 (scaled)
__device__ __half g_kh[(size_t)MROWS * FQK];     // k half, fp16
__device__ __half g_xh[(size_t)MROWS * FIN];     // x in fp16
__device__ __half g_wh[(size_t)NQK * FIN];       // W in fp16
__device__ int    g_rowptr[MAXN + 1];            // CSR row offsets

__device__ __forceinline__ uint32_t smem_u32(const void* p) {
    uint32_t a;
    asm("{ .reg .u64 t; cvta.to.shared.u64 t, %1; cvt.u32.u64 %0, t; }"
        : "=r"(a) : "l"(p));
    return a;
}

// ===========================================================================
// Kernel 0 (fused prologue): convert x -> fp16 (4 float4s/thread for MLP),
// convert W -> fp16, build rowptr. One launch, partitioned by blockIdx.
// ===========================================================================
__device__ __forceinline__ void convert4(const float* __restrict__ src,
                                         __half* __restrict__ dst, int i)
{
    float4 v = ((const float4*)src)[i];
    ((__half2*)dst)[2 * i]     = __halves2half2(__float2half(v.x), __float2half(v.y));
    ((__half2*)dst)[2 * i + 1] = __halves2half2(__float2half(v.z), __float2half(v.w));
}

__global__ __launch_bounds__(256)
void prologue_kernel(const float* __restrict__ x,
                     const float* __restrict__ W,
                     const int* __restrict__ src,
                     __half* __restrict__ xh,
                     __half* __restrict__ wh,
                     int* __restrict__ rowptr,
                     int n4x, int n4w, int E, int N, int XB, int WB)
{
    const int b = blockIdx.x;
    if (b < XB) {
        // 4 independent float4s per thread
        const int base = b * 1024 + threadIdx.x;
#pragma unroll
        for (int u = 0; u < 4; ++u) {
            const int i = base + u * 256;
            if (i < n4x) convert4(x, xh, i);
        }
    } else if (b < XB + WB) {
        const int i = (b - XB) * 256 + threadIdx.x;
        if (i < n4w) convert4(W, wh, i);
    } else {
        const int e = (b - XB - WB) * 256 + threadIdx.x;
        if (e >= E) return;
        const int s = src[e];
        if (e == 0) {
            for (int v = 0; v <= s; ++v) rowptr[v] = 0;
        } else {
            const int sp = src[e - 1];
            for (int v = sp + 1; v <= s; ++v) rowptr[v] = e;
        }
        if (e == E - 1) {
            for (int v = s + 1; v <= N; ++v) rowptr[v] = E;
        }
    }
}

// ===========================================================================
// Kernel 1: qk = x @ W^T via raw ldmatrix + mma.sync.m16n8k16.
// CTA tile 128(m) x 128(n), KC=64, 8 warps as 4x2 (warp = 32x64),
// cp.async double-buffered. Output fp16 (q scaled, k plain).
// ===========================================================================
#define BM 128
#define BN 128
#define KC 64
#define LDS_ 72                  // padded smem leading dim (halves); 144B rows

#define SA_   0
#define SB_   (SA_ + BM * LDS_)              // 9216
#define STAGE_ELEMS (SB_ + BN * LDS_)        // 18432 halves = 36864 B
#define SM_BYTES (STAGE_ELEMS * 2 * 2)       // 73728 B

__device__ __forceinline__ void ldsm_x4(uint32_t* r, uint32_t addr)
{
    asm volatile("ldmatrix.sync.aligned.m8n8.x4.shared.b16 {%0,%1,%2,%3}, [%4];"
        : "=r"(r[0]), "=r"(r[1]), "=r"(r[2]), "=r"(r[3]) : "r"(addr));
}

__device__ __forceinline__ void mma16816(float* d, const uint32_t* a,
                                         const uint32_t* b)
{
    asm volatile("mma.sync.aligned.m16n8k16.row.col.f32.f16.f16.f32 "
        "{%0,%1,%2,%3}, {%4,%5,%6,%7}, {%8,%9}, {%0,%1,%2,%3};"
        : "+f"(d[0]), "+f"(d[1]), "+f"(d[2]), "+f"(d[3])
        : "r"(a[0]), "r"(a[1]), "r"(a[2]), "r"(a[3]), "r"(b[0]), "r"(b[1]));
}

__device__ __forceinline__ void load_stage(__half* sm,
                                           const __half* __restrict__ xh,
                                           const __half* __restrict__ wh,
                                           int m0, int n0, int kc, int tid)
{
#pragma unroll
    for (int i = 0; i < 4; ++i) {
        const int idx = tid + i * 256;           // 0..1023
        const int r = idx >> 3;                  // 0..127
        const int c = (idx & 7) * 8;             // 0..56
        const size_t g = (size_t)(m0 + r) * FIN + kc + c;
        __pipeline_memcpy_async(sm + SA_ + r * LDS_ + c, xh + g, 16);
    }
#pragma unroll
    for (int i = 0; i < 4; ++i) {
        const int idx = tid + i * 256;
        const int r = idx >> 3;
        const int c = (idx & 7) * 8;
        const size_t g = (size_t)(n0 + r) * FIN + kc + c;
        __pipeline_memcpy_async(sm + SB_ + r * LDS_ + c, wh + g, 16);
    }
}

__global__ __launch_bounds__(256)
void gemm_qk_mma(const __half* __restrict__ xh,
                 const __half* __restrict__ wh,
                 __half* __restrict__ qout,
                 __half* __restrict__ kout)
{
    extern __shared__ __half sm[];
    const uint32_t smbase = smem_u32(sm);
    const int tid = threadIdx.x;
    const int wid = tid >> 5;
    const int lane = tid & 31;
    const int warp_m = wid >> 1;          // 0..3
    const int warp_n = wid & 1;           // 0..1
    const int m0  = blockIdx.y * BM;
    const int n0  = blockIdx.x * BN;
    const bool is_q = (n0 < FQK);
    const float scale = is_q ? SCALING : 1.0f;

    float d[2][8][4];
#pragma unroll
    for (int mi = 0; mi < 2; ++mi)
#pragma unroll
        for (int nj = 0; nj < 8; ++nj)
#pragma unroll
            for (int t = 0; t < 4; ++t) d[mi][nj][t] = 0.0f;

    // ldmatrix lane address components (in halves, within a stage)
    const int a_row = warp_m * 32 + (lane & 15);
    const int a_col = (lane >> 4) << 3;                 // 0 or 8
    const int b_row = warp_n * 64 + ((lane >> 4) << 3) + (lane & 7);
    const int b_col = ((lane >> 3) & 1) << 3;           // 0 or 8

    load_stage(sm, xh, wh, m0, n0, 0, tid);
    __pipeline_commit();
    load_stage(sm + STAGE_ELEMS, xh, wh, m0, n0, KC, tid);
    __pipeline_commit();

    const int nChunks = FIN / KC;   // 4
    for (int c = 0; c < nChunks; ++c) {
        __pipeline_wait_prior(1);
        __syncthreads();
        const uint32_t stg = smbase + (uint32_t)((c & 1) * STAGE_ELEMS) * 2;

#pragma unroll
        for (int ks = 0; ks < KC / 16; ++ks) {
            const int k0 = ks * 16;
            uint32_t a[2][4];
#pragma unroll
            for (int mi = 0; mi < 2; ++mi) {
                const uint32_t addr = stg +
                    (uint32_t)((SA_ + (a_row + mi * 16) * LDS_ + a_col + k0) * 2);
                ldsm_x4(a[mi], addr);
            }
            uint32_t b[8][2];
#pragma unroll
            for (int j = 0; j < 4; ++j) {
                uint32_t r[4];
                const uint32_t addr = stg +
                    (uint32_t)((SB_ + (b_row + 16 * j) * LDS_ + b_col + k0) * 2);
                ldsm_x4(r, addr);
                b[2 * j][0] = r[0]; b[2 * j][1] = r[1];
                b[2 * j + 1][0] = r[2]; b[2 * j + 1][1] = r[3];
            }
#pragma unroll
            for (int nj = 0; nj < 8; ++nj)
#pragma unroll
                for (int mi = 0; mi < 2; ++mi)
                    mma16816(d[mi][nj], a[mi], b[nj]);
        }
        __syncthreads();
        if (c + 2 < nChunks) {
            load_stage(sm + (c & 1) * STAGE_ELEMS, xh, wh, m0, n0, (c + 2) * KC, tid);
        }
        __pipeline_commit();
    }

    // ---- epilogue: fp32 acc -> fp16 via per-warp smem scratch (32x64) ----
    __syncthreads();   // mainloop smem reads done; reuse as scratch
    float* buf = (float*)sm + wid * (32 * 64);   // 8 KB per warp, 64 KB total
    __half* outp = is_q ? qout : kout;
    const int col0 = (is_q ? n0 : n0 - FQK) + warp_n * 64;
    const int row0 = m0 + warp_m * 32;

    const int tr = lane >> 2;            // 0..7
    const int tc = 2 * (lane & 3);       // 0,2,4,6
#pragma unroll
    for (int mi = 0; mi < 2; ++mi) {
#pragma unroll
        for (int nj = 0; nj < 8; ++nj) {
            float* p0 = buf + (mi * 16 + tr) * 64 + nj * 8 + tc;
            float* p1 = buf + (mi * 16 + tr + 8) * 64 + nj * 8 + tc;
            p0[0] = d[mi][nj][0] * scale;
            p0[1] = d[mi][nj][1] * scale;
            p1[0] = d[mi][nj][2] * scale;
            p1[1] = d[mi][nj][3] * scale;
        }
    }
    __syncwarp();
#pragma unroll
    for (int r = 0; r < 32; ++r) {
        float a = buf[r * 64 + 2 * lane];
        float b = buf[r * 64 + 2 * lane + 1];
        ((__half2*)(outp + (size_t)(row0 + r) * FQK + col0))[lane] =
            __halves2half2(__float2half(a), __float2half(b));
    }
}

// ===========================================================================
// Kernel 2: fused edge pass (round-12 winner, unchanged).
// One warp per src node; 8 lanes per edge, 4 edges per iteration;
// 2-stage x 4-row cp.async ring in static smem; precomputed rowptr.
// ===========================================================================
#define SMEM_DEG 128

__device__ __forceinline__ float dot_h8(const uint4* q, const uint4* k)
{
    const __half2* qh = (const __half2*)q;
    const __half2* kh2 = (const __half2*)k;
    __half2 a0 = __hmul2(qh[0], kh2[0]);
    __half2 a1 = __hmul2(qh[1], kh2[1]);
    __half2 a2 = __hmul2(qh[2], kh2[2]);
    __half2 a3 = __hmul2(qh[3], kh2[3]);
#pragma unroll
    for (int i = 1; i < 4; ++i) {
        a0 = __hfma2(qh[4 * i + 0], kh2[4 * i + 0], a0);
        a1 = __hfma2(qh[4 * i + 1], kh2[4 * i + 1], a1);
        a2 = __hfma2(qh[4 * i + 2], kh2[4 * i + 2], a2);
        a3 = __hfma2(qh[4 * i + 3], kh2[4 * i + 3], a3);
    }
    float2 f0 = __half22float2(a0);
    float2 f1 = __half22float2(a1);
    float2 f2 = __half22float2(a2);
    float2 f3 = __half22float2(a3);
    return ((f0.x + f0.y) + (f1.x + f1.y)) + ((f2.x + f2.y) + (f3.x + f3.y));
}

__device__ __forceinline__ void fill_stage(__half (*dst)[256],
                                           const __half* __restrict__ kh,
                                           const int* __restrict__ dest,
                                           int j0, int hi, int lane)
{
#pragma unroll
    for (int r = 0; r < 4; ++r) {
        int j = j0 + r;
        if (j >= hi) j = hi - 1;
        const __half* src = kh + (size_t)dest[j] * FQK;
        __pipeline_memcpy_async(&dst[r][lane * 8], src + lane * 8, 16);
    }
}

__global__ __launch_bounds__(256)
void edge_fused_kernel(const int* __restrict__ ei,
                       const int* __restrict__ rowptr,
                       const __half* __restrict__ qh,
                       const __half* __restrict__ kh,
                       float* __restrict__ out,
                       int E, int N)
{
    __shared__ __half kbuf[8][2][4][256];       // 32 KB
    __shared__ float exbuf[8][SMEM_DEG];        // 4 KB

    const int wslot = threadIdx.x >> 5;
    const int node  = (blockIdx.x * blockDim.x + threadIdx.x) >> 5;
    const int lane  = threadIdx.x & 31;
    const int g     = lane >> 3;          // edge slot 0..3
    const int u     = lane & 7;           // chunk owner within 8-lane group
    if (node >= N) return;

    const int lo = rowptr[node];
    const int hi = rowptr[node + 1];
    const int deg = hi - lo;
    if (deg <= 0) return;

    const uint4* qp = (const uint4*)(qh + (size_t)node * FQK);
    uint4 qr[4];
#pragma unroll
    for (int i = 0; i < 4; ++i) qr[i] = qp[u + 8 * i];

    const int* __restrict__ dest = ei + E;
    const int nIter = (deg + 3) >> 2;
    const bool in_smem = (deg <= SMEM_DEG);
    float* exdst = in_smem ? &exbuf[wslot][0] : &out[lo];
    float sum = 0.0f;

    fill_stage(kbuf[wslot][0], kh, dest, lo, hi, lane);
    __pipeline_commit();
    fill_stage(kbuf[wslot][1], kh, dest, lo + 4, hi, lane);
    __pipeline_commit();

    for (int it = 0; it < nIter; ++it) {
        __pipeline_wait_prior(1);
        __syncwarp();

        const uint4* rp = (const uint4*)kbuf[wslot][it & 1][g];
        uint4 cr[4];
#pragma unroll
        for (int i = 0; i < 4; ++i) cr[i] = rp[u + 8 * i];

        __syncwarp();
        fill_stage(kbuf[wslot][it & 1], kh, dest, lo + 4 * (it + 2), hi, lane);
        __pipeline_commit();

        float p = dot_h8(qr, cr);
#pragma unroll
        for (int o = 1; o < 8; o <<= 1)
            p += __shfl_xor_sync(0xffffffffu, p, o);

        const int j = lo + 4 * it + g;
        if (j < hi) {
            float ex = __expf(p);
            sum += ex;
            if (u == 0) exdst[j - lo] = ex;
        }
    }

    sum += __shfl_xor_sync(0xffffffffu, sum, 8);
    sum += __shfl_xor_sync(0xffffffffu, sum, 16);
    const float inv = 1.0f / sum;

    if (in_smem) {
        __syncwarp();
        for (int i = lane; i < deg; i += 32)
            out[lo + i] = exbuf[wslot][i] * inv;
    } else {
        __threadfence_block();
        __syncwarp();
        for (int i = lane; i < deg; i += 32)
            out[lo + i] *= inv;
    }
}

// ===========================================================================
extern "C" void kernel_launch(void* const* d_in, const int* in_sizes, int n_in,
                              void* d_out, int out_size)
{
    const float* x   = (const float*)d_in[0];
    const int*   ei  = (const int*)d_in[1];
    const float* W   = (const float*)d_in[2];
    float*       out = (float*)d_out;

    const int N = in_sizes[0] / FIN;     // 20000
    const int E = in_sizes[1] / 2;       // 640000

    __half* qht; cudaGetSymbolAddress((void**)&qht, g_qh);
    __half* kht; cudaGetSymbolAddress((void**)&kht, g_kh);
    __half* xh;  cudaGetSymbolAddress((void**)&xh,  g_xh);
    __half* wh;  cudaGetSymbolAddress((void**)&wh,  g_wh);
    int* rowptr; cudaGetSymbolAddress((void**)&rowptr, g_rowptr);

    // 0) fused prologue (x convert 4x-unrolled, W convert, rowptr)
    {
        const int n4x = N * FIN / 4;                  // 1,280,000
        const int n4w = NQK * FIN / 4;                // 32,768
        const int XB = (n4x + 1023) / 1024;           // 1250
        const int WB = (n4w + 255) / 256;             // 128
        const int RB = (E + 255) / 256;               // 2500
        prologue_kernel<<<XB + WB + RB, 256>>>(x, W, ei, xh, wh, rowptr,
                                               n4x, n4w, E, N, XB, WB);
    }
    // 1) projection GEMM (raw ldmatrix + mma.sync)
    {
        cudaFuncSetAttribute(gemm_qk_mma,
                             cudaFuncAttributeMaxDynamicSharedMemorySize,
                             SM_BYTES);
        dim3 grid(NQK / BN, MROWS / BM);
        gemm_qk_mma<<<grid, 256, SM_BYTES>>>(xh, wh, qht, kht);
    }
    // 2) fused edge dot + scatter softmax (one warp per node, 2-stage ring)
    {
        int blocks = (N * 32 + 255) / 256;
        edge_fused_kernel<<<blocks, 256>>>(ei, rowptr, qht, kht, out, E, N);
    }
}

// round 17
// speedup vs baseline: 1.3019x; 1.0640x over previous
#include <cuda_runtime.h>
#include <cuda_fp16.h>
#include <cuda_pipeline_primitives.h>
#include <stdint.h>

// Problem constants (fixed by the dataset)
#define FIN   256
#define FQK   256
#define NQK   (2 * FQK)          // 512
#define MAXN  20000
#define MROWS 20096              // 157 * 128, padded for unguarded tiles
#define SCALING 0.0625f          // FQK^-0.5

// Scratch (no allocation allowed in kernel_launch)
__device__ __half g_qh[(size_t)MROWS * FQK];     // q half, fp16 (scaled)
__device__ __half g_kh[(size_t)MROWS * FQK];     // k half, fp16
__device__ __half g_xh[(size_t)MROWS * FIN];     // x in fp16
__device__ __half g_wh[(size_t)NQK * FIN];       // W in fp16
__device__ int    g_rowptr[MAXN + 1];            // CSR row offsets

__device__ __forceinline__ uint32_t smem_u32(const void* p) {
    uint32_t a;
    asm("{ .reg .u64 t; cvta.to.shared.u64 t, %1; cvt.u32.u64 %0, t; }"
        : "=r"(a) : "l"(p));
    return a;
}

// ===========================================================================
// Kernel 0 (fused prologue): convert x -> fp16 (8 float4s/thread for MLP),
// convert W -> fp16, build rowptr. One launch, partitioned by blockIdx.
// ===========================================================================
__device__ __forceinline__ void convert4(const float* __restrict__ src,
                                         __half* __restrict__ dst, int i)
{
    float4 v = ((const float4*)src)[i];
    ((__half2*)dst)[2 * i]     = __halves2half2(__float2half(v.x), __float2half(v.y));
    ((__half2*)dst)[2 * i + 1] = __halves2half2(__float2half(v.z), __float2half(v.w));
}

__global__ __launch_bounds__(256)
void prologue_kernel(const float* __restrict__ x,
                     const float* __restrict__ W,
                     const int* __restrict__ src,
                     __half* __restrict__ xh,
                     __half* __restrict__ wh,
                     int* __restrict__ rowptr,
                     int n4x, int n4w, int E, int N, int XB, int WB)
{
    const int b = blockIdx.x;
    if (b < XB) {
        // 8 independent float4s per thread (MLP 8)
        const int base = b * 2048 + threadIdx.x;
#pragma unroll
        for (int u = 0; u < 8; ++u) {
            const int i = base + u * 256;
            if (i < n4x) convert4(x, xh, i);
        }
    } else if (b < XB + WB) {
        const int i = (b - XB) * 256 + threadIdx.x;
        if (i < n4w) convert4(W, wh, i);
    } else {
        const int e = (b - XB - WB) * 256 + threadIdx.x;
        if (e >= E) return;
        const int s = src[e];
        if (e == 0) {
            for (int v = 0; v <= s; ++v) rowptr[v] = 0;
        } else {
            const int sp = src[e - 1];
            for (int v = sp + 1; v <= s; ++v) rowptr[v] = e;
        }
        if (e == E - 1) {
            for (int v = s + 1; v <= N; ++v) rowptr[v] = E;
        }
    }
}

// ===========================================================================
// Kernel 1: qk = x @ W^T via raw ldmatrix + mma.sync.m16n8k16.
// CTA tile 128(m) x 64(n), KC=64, 8 warps as 4x2 (warp = 32x32) =>
// acc only 32 regs/thread, ~60 total => 4 CTAs/SM (32 warps), no spills.
// cp.async double-buffered. fp16 epilogue staging. Output fp16.
// ===========================================================================
#define BM 128
#define BN 64
#define KC 64
#define LDS_ 72                  // padded smem leading dim (halves); 144B rows

#define SA_   0
#define SB_   (SA_ + BM * LDS_)              // 9216
#define STAGE_ELEMS (SB_ + BN * LDS_)        // 13824 halves = 27648 B
#define SM_BYTES (STAGE_ELEMS * 2 * 2)       // 55296 B

__device__ __forceinline__ void ldsm_x4(uint32_t* r, uint32_t addr)
{
    asm volatile("ldmatrix.sync.aligned.m8n8.x4.shared.b16 {%0,%1,%2,%3}, [%4];"
        : "=r"(r[0]), "=r"(r[1]), "=r"(r[2]), "=r"(r[3]) : "r"(addr));
}

__device__ __forceinline__ void mma16816(float* d, const uint32_t* a,
                                         const uint32_t* b)
{
    asm volatile("mma.sync.aligned.m16n8k16.row.col.f32.f16.f16.f32 "
        "{%0,%1,%2,%3}, {%4,%5,%6,%7}, {%8,%9}, {%0,%1,%2,%3};"
        : "+f"(d[0]), "+f"(d[1]), "+f"(d[2]), "+f"(d[3])
        : "r"(a[0]), "r"(a[1]), "r"(a[2]), "r"(a[3]), "r"(b[0]), "r"(b[1]));
}

__device__ __forceinline__ void load_stage(__half* sm,
                                           const __half* __restrict__ xh,
                                           const __half* __restrict__ wh,
                                           int m0, int n0, int kc, int tid)
{
    // A tile: 128 rows x 64 halves = 1024 16B chunks; 4 per thread
#pragma unroll
    for (int i = 0; i < 4; ++i) {
        const int idx = tid + i * 256;
        const int r = idx >> 3;
        const int c = (idx & 7) * 8;
        const size_t g = (size_t)(m0 + r) * FIN + kc + c;
        __pipeline_memcpy_async(sm + SA_ + r * LDS_ + c, xh + g, 16);
    }
    // B tile: 64 rows x 64 halves = 512 chunks; 2 per thread
#pragma unroll
    for (int i = 0; i < 2; ++i) {
        const int idx = tid + i * 256;
        const int r = idx >> 3;
        const int c = (idx & 7) * 8;
        const size_t g = (size_t)(n0 + r) * FIN + kc + c;
        __pipeline_memcpy_async(sm + SB_ + r * LDS_ + c, wh + g, 16);
    }
}

__global__ __launch_bounds__(256)
void gemm_qk_mma(const __half* __restrict__ xh,
                 const __half* __restrict__ wh,
                 __half* __restrict__ qout,
                 __half* __restrict__ kout)
{
    extern __shared__ __half sm[];
    const uint32_t smbase = smem_u32(sm);
    const int tid = threadIdx.x;
    const int wid = tid >> 5;
    const int lane = tid & 31;
    const int warp_m = wid >> 1;          // 0..3  (32 rows each)
    const int warp_n = wid & 1;           // 0..1  (32 cols each)
    const int m0  = blockIdx.y * BM;
    const int n0  = blockIdx.x * BN;
    const bool is_q = (n0 < FQK);
    const float scale = is_q ? SCALING : 1.0f;

    float d[2][4][4];                     // [mi][nj][reg]: 32 regs
#pragma unroll
    for (int mi = 0; mi < 2; ++mi)
#pragma unroll
        for (int nj = 0; nj < 4; ++nj)
#pragma unroll
            for (int t = 0; t < 4; ++t) d[mi][nj][t] = 0.0f;

    // ldmatrix lane address components (halves, within a stage)
    const int a_row = warp_m * 32 + (lane & 15);
    const int a_col = (lane >> 4) << 3;                 // 0 or 8
    const int b_row = warp_n * 32 + ((lane >> 4) << 3) + (lane & 7);
    const int b_col = ((lane >> 3) & 1) << 3;           // 0 or 8

    load_stage(sm, xh, wh, m0, n0, 0, tid);
    __pipeline_commit();
    load_stage(sm + STAGE_ELEMS, xh, wh, m0, n0, KC, tid);
    __pipeline_commit();

    const int nChunks = FIN / KC;   // 4
    for (int c = 0; c < nChunks; ++c) {
        __pipeline_wait_prior(1);
        __syncthreads();
        const uint32_t stg = smbase + (uint32_t)((c & 1) * STAGE_ELEMS) * 2;

#pragma unroll
        for (int ks = 0; ks < KC / 16; ++ks) {
            const int k0 = ks * 16;
            uint32_t a[2][4];
#pragma unroll
            for (int mi = 0; mi < 2; ++mi) {
                const uint32_t addr = stg +
                    (uint32_t)((SA_ + (a_row + mi * 16) * LDS_ + a_col + k0) * 2);
                ldsm_x4(a[mi], addr);
            }
            // two B ldsm.x4 cover nj 0..3 (each x4 = two n8 fragments)
#pragma unroll
            for (int j = 0; j < 2; ++j) {
                uint32_t r[4];
                const uint32_t addr = stg +
                    (uint32_t)((SB_ + (b_row + 16 * j) * LDS_ + b_col + k0) * 2);
                ldsm_x4(r, addr);
#pragma unroll
                for (int mi = 0; mi < 2; ++mi) {
                    mma16816(d[mi][2 * j],     a[mi], r);
                    mma16816(d[mi][2 * j + 1], a[mi], r + 2);
                }
            }
        }
        __syncthreads();
        if (c + 2 < nChunks) {
            load_stage(sm + (c & 1) * STAGE_ELEMS, xh, wh, m0, n0, (c + 2) * KC, tid);
        }
        __pipeline_commit();
    }

    // ---- epilogue: convert to fp16 in regs, stage 32x32 halves per warp ----
    __syncthreads();   // mainloop smem reads done; reuse as scratch
    __half* buf = sm + wid * (32 * 32);          // 2 KB per warp, 16 KB total
    __half* outp = is_q ? qout : kout;
    const int col0 = (is_q ? n0 : n0 - FQK) + warp_n * 32;
    const int row0 = m0 + warp_m * 32;

    const int tr = lane >> 2;            // 0..7
    const int tc = 2 * (lane & 3);       // 0,2,4,6
#pragma unroll
    for (int mi = 0; mi < 2; ++mi) {
#pragma unroll
        for (int nj = 0; nj < 4; ++nj) {
            __half2 h0 = __halves2half2(__float2half(d[mi][nj][0] * scale),
                                        __float2half(d[mi][nj][1] * scale));
            __half2 h1 = __halves2half2(__float2half(d[mi][nj][2] * scale),
                                        __float2half(d[mi][nj][3] * scale));
            *(__half2*)(buf + (mi * 16 + tr) * 32 + nj * 8 + tc)     = h0;
            *(__half2*)(buf + (mi * 16 + tr + 8) * 32 + nj * 8 + tc) = h1;
        }
    }
    __syncwarp();
    // copy out: 32 rows x 64B = 128 uint4
#pragma unroll
    for (int i = lane; i < 128; i += 32) {
        const int r = i >> 2;
        const int c16 = i & 3;
        uint4 v = *(const uint4*)(buf + r * 32 + c16 * 8);
        *(uint4*)(outp + (size_t)(row0 + r) * FQK + col0 + c16 * 8) = v;
    }
}

// ===========================================================================
// Kernel 2: fused edge pass (round-12 winner, unchanged).
// One warp per src node; 8 lanes per edge, 4 edges per iteration;
// 2-stage x 4-row cp.async ring in static smem; precomputed rowptr.
// ===========================================================================
#define SMEM_DEG 128

__device__ __forceinline__ float dot_h8(const uint4* q, const uint4* k)
{
    const __half2* qh = (const __half2*)q;
    const __half2* kh2 = (const __half2*)k;
    __half2 a0 = __hmul2(qh[0], kh2[0]);
    __half2 a1 = __hmul2(qh[1], kh2[1]);
    __half2 a2 = __hmul2(qh[2], kh2[2]);
    __half2 a3 = __hmul2(qh[3], kh2[3]);
#pragma unroll
    for (int i = 1; i < 4; ++i) {
        a0 = __hfma2(qh[4 * i + 0], kh2[4 * i + 0], a0);
        a1 = __hfma2(qh[4 * i + 1], kh2[4 * i + 1], a1);
        a2 = __hfma2(qh[4 * i + 2], kh2[4 * i + 2], a2);
        a3 = __hfma2(qh[4 * i + 3], kh2[4 * i + 3], a3);
    }
    float2 f0 = __half22float2(a0);
    float2 f1 = __half22float2(a1);
    float2 f2 = __half22float2(a2);
    float2 f3 = __half22float2(a3);
    return ((f0.x + f0.y) + (f1.x + f1.y)) + ((f2.x + f2.y) + (f3.x + f3.y));
}

__device__ __forceinline__ void fill_stage(__half (*dst)[256],
                                           const __half* __restrict__ kh,
                                           const int* __restrict__ dest,
                                           int j0, int hi, int lane)
{
#pragma unroll
    for (int r = 0; r < 4; ++r) {
        int j = j0 + r;
        if (j >= hi) j = hi - 1;
        const __half* src = kh + (size_t)dest[j] * FQK;
        __pipeline_memcpy_async(&dst[r][lane * 8], src + lane * 8, 16);
    }
}

__global__ __launch_bounds__(256)
void edge_fused_kernel(const int* __restrict__ ei,
                       const int* __restrict__ rowptr,
                       const __half* __restrict__ qh,
                       const __half* __restrict__ kh,
                       float* __restrict__ out,
                       int E, int N)
{
    __shared__ __half kbuf[8][2][4][256];       // 32 KB
    __shared__ float exbuf[8][SMEM_DEG];        // 4 KB

    const int wslot = threadIdx.x >> 5;
    const int node  = (blockIdx.x * blockDim.x + threadIdx.x) >> 5;
    const int lane  = threadIdx.x & 31;
    const int g     = lane >> 3;          // edge slot 0..3
    const int u     = lane & 7;           // chunk owner within 8-lane group
    if (node >= N) return;

    const int lo = rowptr[node];
    const int hi = rowptr[node + 1];
    const int deg = hi - lo;
    if (deg <= 0) return;

    const uint4* qp = (const uint4*)(qh + (size_t)node * FQK);
    uint4 qr[4];
#pragma unroll
    for (int i = 0; i < 4; ++i) qr[i] = qp[u + 8 * i];

    const int* __restrict__ dest = ei + E;
    const int nIter = (deg + 3) >> 2;
    const bool in_smem = (deg <= SMEM_DEG);
    float* exdst = in_smem ? &exbuf[wslot][0] : &out[lo];
    float sum = 0.0f;

    fill_stage(kbuf[wslot][0], kh, dest, lo, hi, lane);
    __pipeline_commit();
    fill_stage(kbuf[wslot][1], kh, dest, lo + 4, hi, lane);
    __pipeline_commit();

    for (int it = 0; it < nIter; ++it) {
        __pipeline_wait_prior(1);
        __syncwarp();

        const uint4* rp = (const uint4*)kbuf[wslot][it & 1][g];
        uint4 cr[4];
#pragma unroll
        for (int i = 0; i < 4; ++i) cr[i] = rp[u + 8 * i];

        __syncwarp();
        fill_stage(kbuf[wslot][it & 1], kh, dest, lo + 4 * (it + 2), hi, lane);
        __pipeline_commit();

        float p = dot_h8(qr, cr);
#pragma unroll
        for (int o = 1; o < 8; o <<= 1)
            p += __shfl_xor_sync(0xffffffffu, p, o);

        const int j = lo + 4 * it + g;
        if (j < hi) {
            float ex = __expf(p);
            sum += ex;
            if (u == 0) exdst[j - lo] = ex;
        }
    }

    sum += __shfl_xor_sync(0xffffffffu, sum, 8);
    sum += __shfl_xor_sync(0xffffffffu, sum, 16);
    const float inv = 1.0f / sum;

    if (in_smem) {
        __syncwarp();
        for (int i = lane; i < deg; i += 32)
            out[lo + i] = exbuf[wslot][i] * inv;
    } else {
        __threadfence_block();
        __syncwarp();
        for (int i = lane; i < deg; i += 32)
            out[lo + i] *= inv;
    }
}

// ===========================================================================
extern "C" void kernel_launch(void* const* d_in, const int* in_sizes, int n_in,
                              void* d_out, int out_size)
{
    const float* x   = (const float*)d_in[0];
    const int*   ei  = (const int*)d_in[1];
    const float* W   = (const float*)d_in[2];
    float*       out = (float*)d_out;

    const int N = in_sizes[0] / FIN;     // 20000
    const int E = in_sizes[1] / 2;       // 640000

    __half* qht; cudaGetSymbolAddress((void**)&qht, g_qh);
    __half* kht; cudaGetSymbolAddress((void**)&kht, g_kh);
    __half* xh;  cudaGetSymbolAddress((void**)&xh,  g_xh);
    __half* wh;  cudaGetSymbolAddress((void**)&wh,  g_wh);
    int* rowptr; cudaGetSymbolAddress((void**)&rowptr, g_rowptr);

    // 0) fused prologue (x convert 8x-unrolled, W convert, rowptr)
    {
        const int n4x = N * FIN / 4;                  // 1,280,000
        const int n4w = NQK * FIN / 4;                // 32,768
        const int XB = (n4x + 2047) / 2048;           // 625
        const int WB = (n4w + 255) / 256;             // 128
        const int RB = (E + 255) / 256;               // 2500
        prologue_kernel<<<XB + WB + RB, 256>>>(x, W, ei, xh, wh, rowptr,
                                               n4x, n4w, E, N, XB, WB);
    }
    // 1) projection GEMM (raw mma, BN=64, 4 CTAs/SM)
    {
        cudaFuncSetAttribute(gemm_qk_mma,
                             cudaFuncAttributeMaxDynamicSharedMemorySize,
                             SM_BYTES);
        dim3 grid(NQK / BN, MROWS / BM);
        gemm_qk_mma<<<grid, 256, SM_BYTES>>>(xh, wh, qht, kht);
    }
    // 2) fused edge dot + scatter softmax (one warp per node, 2-stage ring)
    {
        int blocks = (N * 32 + 255) / 256;
        edge_fused_kernel<<<blocks, 256>>>(ei, rowptr, qht, kht, out, E, N);
    }
}